// round 4
// baseline (speedup 1.0000x reference)
#include <cuda_runtime.h>
#include <cstdint>
#include <cstddef>

#define NEGV (-1e30f)

static const int Bn = 128;
static const int Tn = 2048;
static const int Nn = 64;
static const int Ln = 256;

// scratch: per-(b,t) max over n of inputs  (1 MB, device global: allocation-free)
__device__ float g_dmax[128 * 2048];

// ---------------------------------------------------------------------------
// Prep kernel: dmax[b,t] = max_n inputs[b,t,n].  One warp per row of 64.
// ---------------------------------------------------------------------------
__global__ void __launch_bounds__(256) dmax_kernel(const float* __restrict__ in) {
    int gw = (blockIdx.x * 256 + threadIdx.x) >> 5;
    int lane = threadIdx.x & 31;
    if (gw >= Bn * Tn) return;
    const float* p = in + (size_t)gw * Nn;
    float v = fmaxf(p[lane], p[lane + 32]);
#pragma unroll
    for (int o = 16; o > 0; o >>= 1)
        v = fmaxf(v, __shfl_xor_sync(0xffffffffu, v, o));
    if (lane == 0) g_dmax[gw] = v;
}

// ---------------------------------------------------------------------------
// Packed f32x2 helpers (Blackwell: fma.rn.f32x2 only reachable via PTX)
// ---------------------------------------------------------------------------
__device__ __forceinline__ void fma2(unsigned long long& acc,
                                     unsigned long long e,
                                     unsigned long long w) {
    asm("fma.rn.f32x2 %0, %1, %2, %0;" : "+l"(acc) : "l"(e), "l"(w));
}
__device__ __forceinline__ unsigned long long add2(unsigned long long a,
                                                   unsigned long long b) {
    unsigned long long r;
    asm("add.rn.f32x2 %0, %1, %2;" : "=l"(r) : "l"(a), "l"(b));
    return r;
}

__device__ __forceinline__ void cp4(void* dst, const void* src) {
    unsigned int d = (unsigned int)__cvta_generic_to_shared(dst);
    asm volatile("cp.async.ca.shared.global [%0], [%1], 4;" :: "r"(d), "l"(src) : "memory");
}
#define CP_COMMIT() asm volatile("cp.async.commit_group;" ::: "memory")
#define CP_WAIT5()  asm volatile("cp.async.wait_group 5;" ::: "memory")

// ---------------------------------------------------------------------------
// Main kernel: one CTA per batch. 192 threads:
//   tid  0..63  : fcc lanes (thread = emission class n), scaled-exp domain
//   tid 64..191 : fac lanes (thread = 2 target positions), log domain
//   tid 64..127 also run the cp.async staging ring for x_t (+ dmax)
// ---------------------------------------------------------------------------
__global__ void __launch_bounds__(192, 1) asg_kernel(
    const float* __restrict__ xin_all, const int* __restrict__ tgt_all,
    const int* __restrict__ tsz_all, const float* __restrict__ trans,
    float* __restrict__ out)
{
    __shared__ __align__(16) float sh_x[8][64];   // x_t staging ring
    __shared__ float sh_d[8];                     // dmax staging ring
    __shared__ __align__(16) float sh_E[2][64];   // fcc state, double buffered
    __shared__ float sh_fb[2][4];                 // fac warp-boundary alpha, dbl buf
    __shared__ float sh_wm[2];                    // renorm warp maxes
    __shared__ float sh_fac;

    const int b = blockIdx.x;
    const int tid = threadIdx.x;
    const float* xin = xin_all + (size_t)b * Tn * Nn;
    const float* dmx = g_dmax + b * Tn;

    unsigned long long w2[32];                    // exp(trans[n, :]) packed (fcc only)
    float c = 0.f;                                // running log-scale (tid 0 only)
    float a0 = NEGV, a1 = NEGV;                   // fac alphas
    float ts0 = 0.f, ts1 = 0.f, tm0 = 0.f, tm1 = 0.f;
    int tg0 = 0, tg1 = 0, tssel = 0;

    if (tid < 64) {
        const int n = tid;
        const float* wr = trans + n * Nn;
#pragma unroll
        for (int j = 0; j < 32; j++) {
            float wa = __expf(wr[2 * j]);
            float wb = __expf(wr[2 * j + 1]);
            asm("mov.b64 %0, {%1, %2};" : "=l"(w2[j]) : "f"(wa), "f"(wb));
        }
        float d0 = dmx[0];
        sh_E[0][n] = __expf(xin[n] - d0);   // alpha0 = x0
        if (tid == 0) c = d0;
    } else {
        const int f = tid - 64;
        const int l0 = 2 * f, l1 = 2 * f + 1;
        tg0 = tgt_all[b * Ln + l0];
        tg1 = tgt_all[b * Ln + l1];
        int tgm = (l0 > 0) ? tgt_all[b * Ln + l0 - 1] : 0;
        ts0 = trans[tg0 * Nn + tg0];
        ts1 = trans[tg1 * Nn + tg1];
        tm0 = trans[tg0 * Nn + tgm];        // move into l0 (unused when l0==0)
        tm1 = trans[tg1 * Nn + tg0];        // move into l1
        tssel = tsz_all[b];
        a0 = (l0 == 0) ? xin[tg0] : NEGV;   // alpha0[0] = x0[target[0]]
        a1 = NEGV;
        if ((f & 31) == 31) sh_fb[0][f >> 5] = a1;
        if (f < 64) {
            // prologue: stage x_t for t = 1..6
#pragma unroll
            for (int tt = 1; tt <= 6; tt++) {
                cp4(&sh_x[tt & 7][f], xin + (size_t)tt * Nn + f);
                if (f == 0) cp4(&sh_d[tt & 7], dmx + tt);
                CP_COMMIT();
            }
            CP_WAIT5();
        }
    }
    __syncthreads();

    for (int t = 1; t < Tn; ++t) {
        const int rs = t & 7;
        const int rb = (t + 1) & 1;   // E read buffer
        const int wb = t & 1;         // E write buffer

        if (tid < 64) {
            // ---- fcc: S[n] = sum_{m=0}^{63} E[m] * expTrans[n][m] ----
            // 16 x ulonglong2 covers all 64 floats of E; 32 packed f32x2 FMAs.
            const ulonglong2* ep = reinterpret_cast<const ulonglong2*>(sh_E[rb]);
            unsigned long long acc0 = 0ull, acc1 = 0ull, acc2 = 0ull, acc3 = 0ull;
#pragma unroll
            for (int k = 0; k < 16; k += 2) {
                ulonglong2 ea = ep[k];       // E[4k .. 4k+3]   (broadcast LDS.128)
                ulonglong2 eb = ep[k + 1];   // E[4k+4 .. 4k+7]
                fma2(acc0, ea.x, w2[2 * k]);
                fma2(acc1, ea.y, w2[2 * k + 1]);
                fma2(acc2, eb.x, w2[2 * k + 2]);
                fma2(acc3, eb.y, w2[2 * k + 3]);
            }
            unsigned long long s = add2(add2(acc0, acc1), add2(acc2, acc3));
            float slo, shi;
            asm("mov.b64 {%0, %1}, %2;" : "=f"(slo), "=f"(shi) : "l"(s));
            float S = slo + shi;

            float xv = sh_x[rs][tid];
            float dv = sh_d[rs];
            float arg = xv - dv;
            if ((t & 7) == 1 && t > 8) {          // consume stale renorm max
                float M = fmaxf(sh_wm[0], sh_wm[1]);
                float lm = __logf(M);
                arg -= lm;
                if (tid == 0) c += lm;
            }
            float En = S * __expf(arg);
            if (tid == 0) c += dv;
            if ((t & 7) == 0) {                   // capture renorm max
                float m = En;
#pragma unroll
                for (int o = 16; o > 0; o >>= 1)
                    m = fmaxf(m, __shfl_xor_sync(0xffffffffu, m, o));
                if ((tid & 31) == 0) sh_wm[tid >> 5] = m;
            }
            sh_E[wb][tid] = En;
        } else {
            // ---- fac: log-domain, 2 target positions per thread ----
            const int f = tid - 64;
            float e0 = sh_x[rs][tg0];
            float e1 = sh_x[rs][tg1];
            float ap = __shfl_up_sync(0xffffffffu, a1, 1);
            if ((f & 31) == 0) ap = (f == 0) ? NEGV : sh_fb[rb][(f >> 5) - 1];

            float st0 = a0 + ts0, mv0 = ap + tm0;
            float h0 = fmaxf(st0, mv0), l0v = fminf(st0, mv0);
            float na0 = e0 + h0 + __logf(1.0f + __expf(l0v - h0));

            float st1 = a1 + ts1, mv1 = a0 + tm1;   // uses OLD a0
            float h1 = fmaxf(st1, mv1), l1v = fminf(st1, mv1);
            float na1 = e1 + h1 + __logf(1.0f + __expf(l1v - h1));

            a0 = na0; a1 = na1;
            if ((f & 31) == 31) sh_fb[wb][f >> 5] = a1;

            if (f < 64) {                         // staging ring
                int tpf = t + 6; if (tpf > Tn - 1) tpf = Tn - 1;
                cp4(&sh_x[(t + 6) & 7][f], xin + (size_t)tpf * Nn + f);
                if (f == 0) cp4(&sh_d[(t + 6) & 7], dmx + tpf);
                CP_COMMIT();
                CP_WAIT5();
            }
        }
        __syncthreads();
    }

    // ---- epilogue ----
    if (tid >= 64) {
        const int f = tid - 64;
        if (2 * f == tssel - 1)     sh_fac = a0;
        if (2 * f + 1 == tssel - 1) sh_fac = a1;
    }
    __syncthreads();
    if (tid < 32) {
        float v = sh_E[1][tid] + sh_E[1][tid + 32];   // last write was wb = 2047&1 = 1
#pragma unroll
        for (int o = 16; o > 0; o >>= 1)
            v += __shfl_xor_sync(0xffffffffu, v, o);
        if (tid == 0) out[b] = (c + __logf(v)) - sh_fac;
    }
}

// ---------------------------------------------------------------------------
extern "C" void kernel_launch(void* const* d_in, const int* in_sizes, int n_in,
                              void* d_out, int out_size) {
    const float* in    = (const float*)d_in[0];   // input  [B,T,N] f32
    const int*   tgt   = (const int*)  d_in[1];   // target [B,L]   i32
    const int*   tsz   = (const int*)  d_in[2];   // target_size [B]
    const float* trans = (const float*)d_in[3];   // trans  [N,N]   f32
    float* out = (float*)d_out;
    (void)in_sizes; (void)n_in; (void)out_size;

    dmax_kernel<<<(Bn * Tn) / 8, 256>>>(in);
    asg_kernel<<<Bn, 192>>>(in, tgt, tsz, trans, out);
}

// round 5
// speedup vs baseline: 1.3292x; 1.3292x over previous
#include <cuda_runtime.h>
#include <cstdint>
#include <cstddef>

#define NEGV (-1e30f)

static const int Bn = 128;
static const int Tn = 2048;
static const int Nn = 64;
static const int Ln = 256;

// result scratch (device globals: allocation-free)
__device__ float g_fcc[Bn];
__device__ float g_fac[Bn];

// ---------------------------------------------------------------------------
// Packed f32x2 helpers (Blackwell: fma.rn.f32x2 only reachable via PTX)
// ---------------------------------------------------------------------------
__device__ __forceinline__ void fma2(unsigned long long& acc,
                                     unsigned long long e,
                                     unsigned long long w) {
    asm("fma.rn.f32x2 %0, %1, %2, %0;" : "+l"(acc) : "l"(e), "l"(w));
}
__device__ __forceinline__ unsigned long long add2(unsigned long long a,
                                                   unsigned long long b) {
    unsigned long long r;
    asm("add.rn.f32x2 %0, %1, %2;" : "=l"(r) : "l"(a), "l"(b));
    return r;
}
__device__ __forceinline__ void cp4(void* dst, const void* src) {
    unsigned int d = (unsigned int)__cvta_generic_to_shared(dst);
    asm volatile("cp.async.ca.shared.global [%0], [%1], 4;" :: "r"(d), "l"(src) : "memory");
}
#define CP_COMMIT() asm volatile("cp.async.commit_group;" ::: "memory")
#define CP_WAIT5()  asm volatile("cp.async.wait_group 5;" ::: "memory")

// ---------------------------------------------------------------------------
// Main kernel, grid 256 x 128 threads.
//   blocks   0..127 : fcc for batch b (64 live threads, thread = class n)
//   blocks 128..255 : fac for batch b (128 threads, thread = 2 target lanes)
// The two roles are fully independent -> private small barriers, co-resident.
// ---------------------------------------------------------------------------
__global__ void __launch_bounds__(128, 1) asg_main(
    const float* __restrict__ xin_all, const int* __restrict__ tgt_all,
    const int* __restrict__ tsz_all, const float* __restrict__ trans)
{
    __shared__ __align__(16) float sx[8][64];     // x_t staging ring
    __shared__ __align__(16) float sE[2][64];     // fcc state, double buffered
    __shared__ float sfb[2][4];                   // fac warp-boundary, dbl buf

    const int role = blockIdx.x >> 7;             // 0: fcc, 1: fac
    const int b = blockIdx.x & 127;
    const int tid = threadIdx.x;
    const float* xin = xin_all + (size_t)b * Tn * Nn;

    if (role == 0) {
        // ================= fcc: scaled-exp forward scan ====================
        if (tid >= 64) return;                    // 2-warp CTA
        const int n = tid;

        unsigned long long w2[32];                // exp(trans[n, :]) packed
        const float* wr = trans + n * Nn;
#pragma unroll
        for (int j = 0; j < 32; j++) {
            float wa = __expf(wr[2 * j]);
            float wb = __expf(wr[2 * j + 1]);
            asm("mov.b64 %0, {%1, %2};" : "=l"(w2[j]) : "f"(wa), "f"(wb));
        }
        sE[0][n] = __expf(xin[n]);                // alpha0 = x0, c = 0
        float c = 0.f;

        // prologue: stage x_t for t = 1..6
#pragma unroll
        for (int tt = 1; tt <= 6; tt++) {
            cp4(&sx[tt & 7][n], xin + (size_t)tt * Nn + n);
            CP_COMMIT();
        }
        CP_WAIT5();
        __syncthreads();

        for (int t = 1; t < Tn; ++t) {
            const int rs = t & 7;
            const int rb = (t + 1) & 1;           // E read buffer
            const int wbuf = t & 1;               // E write buffer

            const ulonglong2* ep = reinterpret_cast<const ulonglong2*>(sE[rb]);
            ulonglong2 ea = ep[0];
            float e0lo, e0hi;
            asm("mov.b64 {%0, %1}, %2;" : "=f"(e0lo), "=f"(e0hi) : "l"(ea.x));
            float lm = __logf(e0lo);              // per-step renorm: ln E_prev[0]

            unsigned long long acc0 = 0ull, acc1 = 0ull, acc2 = 0ull, acc3 = 0ull;
            fma2(acc0, ea.x, w2[0]);
            fma2(acc1, ea.y, w2[1]);
#pragma unroll
            for (int k = 1; k < 16; k++) {
                ulonglong2 e = ep[k];             // broadcast LDS.128
                if (k & 1) {
                    fma2(acc2, e.x, w2[2 * k]);
                    fma2(acc3, e.y, w2[2 * k + 1]);
                } else {
                    fma2(acc0, e.x, w2[2 * k]);
                    fma2(acc1, e.y, w2[2 * k + 1]);
                }
            }
            unsigned long long s = add2(add2(acc0, acc1), add2(acc2, acc3));
            float slo, shi;
            asm("mov.b64 {%0, %1}, %2;" : "=f"(slo), "=f"(shi) : "l"(s));
            float S = slo + shi;

            float xv = sx[rs][n];
            float En = S * __expf(xv - lm);       // E' = S * exp(x) / E_prev[0]
            c += lm;                              // identical in all threads
            sE[wbuf][n] = En;

            int tpf = t + 6; if (tpf > Tn - 1) tpf = Tn - 1;
            cp4(&sx[(t + 6) & 7][n], xin + (size_t)tpf * Nn + n);
            CP_COMMIT();
            CP_WAIT5();
            __syncthreads();
        }

        // epilogue: fcc = c + ln(sum_n E[n]);  last write buffer = 2047&1 = 1
        if (tid < 32) {
            float v = sE[1][tid] + sE[1][tid + 32];
#pragma unroll
            for (int o = 16; o > 0; o >>= 1)
                v += __shfl_xor_sync(0xffffffffu, v, o);
            if (tid == 0) g_fcc[b] = c + __logf(v);
        }
    } else {
        // ================= fac: log-domain constrained scan ================
        const int f = tid;                        // 0..127, lanes 2f, 2f+1
        const int l0 = 2 * f, l1 = 2 * f + 1;
        const int tg0 = tgt_all[b * Ln + l0];
        const int tg1 = tgt_all[b * Ln + l1];
        const int tgm = (l0 > 0) ? tgt_all[b * Ln + l0 - 1] : 0;
        const float ts0 = trans[tg0 * Nn + tg0];
        const float ts1 = trans[tg1 * Nn + tg1];
        const float tm0 = trans[tg0 * Nn + tgm];  // move into l0 (unused if l0==0)
        const float tm1 = trans[tg1 * Nn + tg0];  // move into l1
        const int tssel = tsz_all[b];

        float a0 = (l0 == 0) ? xin[tg0] : NEGV;   // alpha0[0] = x0[target[0]]
        float a1 = NEGV;
        if ((f & 31) == 31) sfb[0][f >> 5] = a1;

        if (f < 64) {
#pragma unroll
            for (int tt = 1; tt <= 6; tt++) {
                cp4(&sx[tt & 7][f], xin + (size_t)tt * Nn + f);
                CP_COMMIT();
            }
            CP_WAIT5();
        }
        __syncthreads();

        for (int t = 1; t < Tn; ++t) {
            const int rs = t & 7;
            const int rb = (t + 1) & 1;
            const int wbuf = t & 1;

            float e0 = sx[rs][tg0];
            float e1 = sx[rs][tg1];
            float ap = __shfl_up_sync(0xffffffffu, a1, 1);
            if ((f & 31) == 0) ap = (f == 0) ? NEGV : sfb[rb][(f >> 5) - 1];

            float st0 = a0 + ts0, mv0 = ap + tm0;
            float h0 = fmaxf(st0, mv0), lo0 = fminf(st0, mv0);
            float na0 = e0 + h0 + __logf(1.0f + __expf(lo0 - h0));

            float st1 = a1 + ts1, mv1 = a0 + tm1; // uses OLD a0
            float h1 = fmaxf(st1, mv1), lo1 = fminf(st1, mv1);
            float na1 = e1 + h1 + __logf(1.0f + __expf(lo1 - h1));

            a0 = na0; a1 = na1;
            if ((f & 31) == 31) sfb[wbuf][f >> 5] = a1;

            if (f < 64) {
                int tpf = t + 6; if (tpf > Tn - 1) tpf = Tn - 1;
                cp4(&sx[(t + 6) & 7][f], xin + (size_t)tpf * Nn + f);
                CP_COMMIT();
                CP_WAIT5();
            }
            __syncthreads();
        }

        if (l0 == tssel - 1) g_fac[b] = a0;
        if (l1 == tssel - 1) g_fac[b] = a1;
    }
}

// ---------------------------------------------------------------------------
__global__ void __launch_bounds__(128) combine_kernel(float* __restrict__ out) {
    int i = threadIdx.x;
    out[i] = g_fcc[i] - g_fac[i];
}

// ---------------------------------------------------------------------------
extern "C" void kernel_launch(void* const* d_in, const int* in_sizes, int n_in,
                              void* d_out, int out_size) {
    const float* in    = (const float*)d_in[0];   // input  [B,T,N] f32
    const int*   tgt   = (const int*)  d_in[1];   // target [B,L]   i32
    const int*   tsz   = (const int*)  d_in[2];   // target_size [B]
    const float* trans = (const float*)d_in[3];   // trans  [N,N]   f32
    float* out = (float*)d_out;
    (void)in_sizes; (void)n_in; (void)out_size;

    asg_main<<<2 * Bn, 128>>>(in, tgt, tsz, trans);
    combine_kernel<<<1, 128>>>(out);
}